// round 7
// baseline (speedup 1.0000x reference)
#include <cuda_runtime.h>
#include <cuda_fp16.h>
#include <cstdint>

#define H_DIM 1024
#define S_DIM 2048
#define B_DIM 32
#define M_TILE 128
#define N_PASS 256
#define NUM_PASSES 4
#define KC 64
#define NUM_KCH 16          // H_DIM / KC

// smem layout (dynamic)
#define SMEM_DVEC 0
#define SMEM_VA   4096
#define SMEM_SCORE 8192     // 128 floats
#define SMEM_STAGES 9216
#define SMEM_B_OFF 16384    // within stage: A 16KB then B 32KB
#define STAGE_SZ  49152
#define SMEM_TOTAL (SMEM_STAGES + 2 * STAGE_SZ)   // 107520

__device__ __align__(16) __half g_a[(size_t)B_DIM * S_DIM * H_DIM];   // enc as fp16, 128MB
__device__ __align__(16) __half g_ut[(size_t)H_DIM * H_DIM];          // Ua^T as fp16, 2MB
__device__ float g_dvec[B_DIM * H_DIM];

__device__ __forceinline__ uint32_t smem_u32(const void* p) {
    uint32_t a;
    asm("{ .reg .u64 t; cvta.to.shared.u64 t, %1; cvt.u32.u64 %0, t; }" : "=r"(a) : "l"(p));
    return a;
}
__device__ __forceinline__ void cp16(uint32_t s, const void* g) {
    asm volatile("cp.async.cg.shared.global [%0], [%1], 16;" :: "r"(s), "l"(g));
}
#define CP_COMMIT() asm volatile("cp.async.commit_group;" ::: "memory")
#define CP_WAIT1()  asm volatile("cp.async.wait_group 1;" ::: "memory")

__device__ __forceinline__ void ldm4(uint32_t& r0, uint32_t& r1, uint32_t& r2, uint32_t& r3,
                                     uint32_t a) {
    asm volatile("ldmatrix.sync.aligned.m8n8.x4.shared.b16 {%0,%1,%2,%3}, [%4];"
                 : "=r"(r0), "=r"(r1), "=r"(r2), "=r"(r3) : "r"(a));
}
__device__ __forceinline__ void mma16816(float* c, const uint32_t* a, uint32_t b0, uint32_t b1) {
    asm volatile("mma.sync.aligned.m16n8k16.row.col.f32.f16.f16.f32 "
                 "{%0,%1,%2,%3}, {%4,%5,%6,%7}, {%8,%9}, {%0,%1,%2,%3};"
                 : "+f"(c[0]), "+f"(c[1]), "+f"(c[2]), "+f"(c[3])
                 : "r"(a[0]), "r"(a[1]), "r"(a[2]), "r"(a[3]), "r"(b0), "r"(b1));
}

// FMA/ALU-only tanh: exp2 range reduction + deg-5 poly + bit-trick scale + Newton rcp.
// abs err <= ~3e-5 on all inputs; NO MUFU ops (67M MUFU tanh would cost ~530us chip-wide).
__device__ __forceinline__ float fast_tanh(float x) {
    x = fminf(9.0f, fmaxf(-9.0f, x));
    const float C = 2.885390082f;            // 2*log2(e)
    float zm = fmaf(x, C, 12582912.0f);      // round-to-nearest via magic
    int nb = __float_as_int(zm);             // 0x4B400000 + n
    float nf = zm - 12582912.0f;
    float f = fmaf(x, C, -nf);               // f in [-0.5, 0.5]
    float p = 1.3333558e-3f;
    p = fmaf(p, f, 9.6181291e-3f);
    p = fmaf(p, f, 5.5504109e-2f);
    p = fmaf(p, f, 2.4022651e-1f);
    p = fmaf(p, f, 6.9314718e-1f);
    p = fmaf(p, f, 1.0f);                    // 2^f
    float E = p * __int_as_float((nb + (127 - 0x4B400000)) << 23);  // e^{2x}
    float D = E + 1.0f;
    float r = __int_as_float((int)(0x7EF127EAu - (uint32_t)__float_as_int(D)));
    r = r * fmaf(-D, r, 2.0f);
    r = r * fmaf(-D, r, 2.0f);
    r = r * fmaf(-D, r, 2.0f);               // r = 1/(E+1), err ~1e-10
    return fmaf(-2.0f, r, 1.0f);             // 1 - 2/(E+1)
}

// ---------------- enc fp32 -> fp16 ----------------
__global__ void __launch_bounds__(256) enc_split_kernel(const float* __restrict__ enc) {
    size_t i = (size_t)blockIdx.x * 256 + threadIdx.x;   // 16,777,216 float4s
    float4 v = ((const float4*)enc)[i];
    __half2 h0 = __floats2half2_rn(v.x, v.y);
    __half2 h1 = __floats2half2_rn(v.z, v.w);
    ((uint2*)g_a)[i] = make_uint2(*(uint32_t*)&h0, *(uint32_t*)&h1);
}

// ---------------- Ut[k][h] = Ua[h][k] as fp16 ----------------
__global__ void ut_split_kernel(const float* __restrict__ ua_w) {
    __shared__ float tile[32][33];
    int tx = threadIdx.x, ty = threadIdx.y;
    int k = blockIdx.x * 32 + tx, h0 = blockIdx.y * 32;
    #pragma unroll
    for (int i = 0; i < 32; i += 8)
        tile[ty + i][tx] = ua_w[(size_t)(h0 + ty + i) * H_DIM + k];
    __syncthreads();
    #pragma unroll
    for (int i = 0; i < 32; i += 8) {
        int kk = blockIdx.x * 32 + ty + i;
        g_ut[(size_t)kk * H_DIM + h0 + tx] = __float2half(tile[tx][ty + i]);
    }
}

// ---------------- dvec[b,k] = Wa_b[k]+Ua_b[k] + sum_h dec[b,h]*Wa[h,k] ----------------
__global__ void __launch_bounds__(256) dvec_kernel(
    const float* __restrict__ dec, const float* __restrict__ wa_w,
    const float* __restrict__ wa_b, const float* __restrict__ ua_b) {
    __shared__ float ds[H_DIM];
    int b = blockIdx.x >> 2, kc = blockIdx.x & 3, tid = threadIdx.x;
    #pragma unroll
    for (int i = 0; i < 4; ++i) ds[tid + i * 256] = dec[b * H_DIM + tid + i * 256];
    __syncthreads();
    int k = kc * 256 + tid;
    float acc = wa_b[k] + ua_b[k];
    #pragma unroll 8
    for (int h = 0; h < H_DIM; ++h) acc += ds[h] * __ldg(&wa_w[(size_t)h * H_DIM + k]);
    g_dvec[b * H_DIM + k] = acc;
}

// ---------------- fused GEMM (mma.sync fp16) + tanh + Va-dot -> raw scores ----------------
__global__ void __launch_bounds__(256, 1) gemm_kernel(
    const float* __restrict__ va_w, float* __restrict__ scores) {
    extern __shared__ __align__(128) char smem[];
    uint32_t sb = smem_u32(smem);
    int tid = threadIdx.x;
    int lane = tid & 31, wid = tid >> 5;
    int warp_m = wid >> 2, warp_n = wid & 3;         // 2 x 4 warp grid
    int m0 = blockIdx.x * M_TILE;
    int bidx = m0 >> 11;

    // persistent smem: dvec row (this b), Va, score accumulator
    ((float4*)(smem + SMEM_DVEC))[tid] = ((const float4*)(g_dvec + bidx * H_DIM))[tid];
    ((float4*)(smem + SMEM_VA))[tid] = ((const float4*)va_w)[tid];
    float* s_score = (float*)(smem + SMEM_SCORE);
    if (tid < 128) s_score[tid] = 0.f;
    __syncthreads();
    const float* smd = (const float*)(smem + SMEM_DVEC);
    const float* smv = (const float*)(smem + SMEM_VA);

    // ldmatrix lane decomposition (row&7 == r8 always: bases are multiples of 8)
    int r8 = lane & 7, sel = lane >> 3;
    int selb = (sel & 1) << 3, selc = sel >> 1;
    uint32_t aRowBase = warp_m * 64 + selb + r8;
    uint32_t bRowBase = warp_n * 64 + selb + r8;

    float acc[4][8][4] = {};
    float partial[8] = {};

    for (int pass = 0; pass < NUM_PASSES; ++pass) {
        int n0 = pass * N_PASS;

        auto fill = [&](int s, int kc) {
            uint32_t base = sb + SMEM_STAGES + s * STAGE_SZ;
            int k0 = kc * KC;
            #pragma unroll
            for (int i = 0; i < 4; ++i) {             // A: 128 rows x 8 chunks
                int idx = tid + i * 256;
                int row = idx >> 3, ch = idx & 7;
                cp16(base + row * 128 + ((ch ^ (row & 7)) << 4),
                     g_a + (size_t)(m0 + row) * H_DIM + k0 + ch * 8);
            }
            #pragma unroll
            for (int i = 0; i < 8; ++i) {             // B: 256 rows x 8 chunks
                int idx = tid + i * 256;
                int row = idx >> 3, ch = idx & 7;
                cp16(base + SMEM_B_OFF + row * 128 + ((ch ^ (row & 7)) << 4),
                     g_ut + (size_t)(n0 + row) * H_DIM + k0 + ch * 8);
            }
        };

        fill(0, 0); CP_COMMIT();
        fill(1, 1); CP_COMMIT();

        for (int kc = 0; kc < NUM_KCH; ++kc) {
            CP_WAIT1();
            __syncthreads();
            int buf = kc & 1;
            uint32_t sA = sb + SMEM_STAGES + buf * STAGE_SZ;
            uint32_t sB = sA + SMEM_B_OFF;
            #pragma unroll
            for (int ks = 0; ks < 4; ++ks) {
                uint32_t csw = (uint32_t)(((ks * 2 + selc) ^ r8) << 4);
                uint32_t a[4][4], b[4][4];
                #pragma unroll
                for (int mf = 0; mf < 4; ++mf)
                    ldm4(a[mf][0], a[mf][1], a[mf][2], a[mf][3],
                         sA + (aRowBase + mf * 16) * 128 + csw);
                #pragma unroll
                for (int nf2 = 0; nf2 < 4; ++nf2)
                    ldm4(b[nf2][0], b[nf2][1], b[nf2][2], b[nf2][3],
                         sB + (bRowBase + nf2 * 16) * 128 + csw);
                #pragma unroll
                for (int mf = 0; mf < 4; ++mf)
                    #pragma unroll
                    for (int nf = 0; nf < 8; ++nf)
                        mma16816(acc[mf][nf], a[mf], b[nf >> 1][nf & 1], b[nf >> 1][(nf & 1) + 2]);
            }
            __syncthreads();
            if (kc + 2 < NUM_KCH) fill(buf, kc + 2);
            CP_COMMIT();
        }

        // epilogue: tanh(acc + dvec) . Va -> per-thread row partials; reset accums
        #pragma unroll
        for (int mf = 0; mf < 4; ++mf) {
            #pragma unroll
            for (int nf = 0; nf < 8; ++nf) {
                int col = n0 + warp_n * 64 + nf * 8 + (lane & 3) * 2;
                float* c = acc[mf][nf];
                partial[mf * 2 + 0] += smv[col]     * fast_tanh(c[0] + smd[col]) +
                                       smv[col + 1] * fast_tanh(c[1] + smd[col + 1]);
                partial[mf * 2 + 1] += smv[col]     * fast_tanh(c[2] + smd[col]) +
                                       smv[col + 1] * fast_tanh(c[3] + smd[col + 1]);
                c[0] = c[1] = c[2] = c[3] = 0.f;
            }
        }
    }

    // reduce partials: quad shuffle then smem atomics across warp_n
    #pragma unroll
    for (int p = 0; p < 8; ++p) {
        float v = partial[p];
        v += __shfl_xor_sync(0xFFFFFFFFu, v, 1);
        v += __shfl_xor_sync(0xFFFFFFFFu, v, 2);
        if ((lane & 3) == 0) {
            int row = warp_m * 64 + (p >> 1) * 16 + (p & 1) * 8 + (lane >> 2);
            atomicAdd(&s_score[row], v);
        }
    }
    __syncthreads();
    if (tid < 128) scores[m0 + tid] = s_score[tid];
}

// ---------------- masked softmax over S, in place ----------------
__global__ void __launch_bounds__(256) softmax_kernel(
    const int* __restrict__ mask, float* __restrict__ out) {
    __shared__ float red[8];
    int b = blockIdx.x, tid = threadIdx.x, wid = tid >> 5, lid = tid & 31;
    float v[8], mx = -3.0e38f;
    #pragma unroll
    for (int i = 0; i < 8; ++i) {
        int s = tid + i * 256;
        float x = out[b * S_DIM + s];
        if (mask[b * S_DIM + s] == 0) x = -1e9f;
        v[i] = x; mx = fmaxf(mx, x);
    }
    #pragma unroll
    for (int o = 16; o > 0; o >>= 1) mx = fmaxf(mx, __shfl_xor_sync(0xFFFFFFFFu, mx, o));
    if (lid == 0) red[wid] = mx;
    __syncthreads();
    mx = red[0];
    #pragma unroll
    for (int w = 1; w < 8; ++w) mx = fmaxf(mx, red[w]);
    float sum = 0.f;
    #pragma unroll
    for (int i = 0; i < 8; ++i) { v[i] = expf(v[i] - mx); sum += v[i]; }
    #pragma unroll
    for (int o = 16; o > 0; o >>= 1) sum += __shfl_xor_sync(0xFFFFFFFFu, sum, o);
    __syncthreads();
    if (lid == 0) red[wid] = sum;
    __syncthreads();
    sum = 0.f;
    #pragma unroll
    for (int w = 0; w < 8; ++w) sum += red[w];
    float inv = 1.f / sum;
    #pragma unroll
    for (int i = 0; i < 8; ++i) out[b * S_DIM + tid + i * 256] = v[i] * inv;
}

extern "C" void kernel_launch(void* const* d_in, const int* in_sizes, int n_in,
                              void* d_out, int out_size) {
    const float* dec  = (const float*)d_in[0];
    const float* enc  = (const float*)d_in[1];
    const int*   mask = (const int*)d_in[2];
    const float* wa_w = (const float*)d_in[3];
    const float* wa_b = (const float*)d_in[4];
    const float* ua_w = (const float*)d_in[5];
    const float* ua_b = (const float*)d_in[6];
    const float* va_w = (const float*)d_in[7];
    float* out = (float*)d_out;

    cudaFuncSetAttribute(gemm_kernel, cudaFuncAttributeMaxDynamicSharedMemorySize, SMEM_TOTAL);

    enc_split_kernel<<<(B_DIM * S_DIM * H_DIM) / (4 * 256), 256>>>(enc);
    ut_split_kernel<<<dim3(32, 32), dim3(32, 8)>>>(ua_w);
    dvec_kernel<<<B_DIM * 4, 256>>>(dec, wa_w, wa_b, ua_b);
    gemm_kernel<<<(B_DIM * S_DIM) / M_TILE, 256, SMEM_TOTAL>>>(va_w, out);
    softmax_kernel<<<B_DIM, 256>>>(mask, out);
}

// round 10
// speedup vs baseline: 1.0169x; 1.0169x over previous
#include <cuda_runtime.h>
#include <cuda_fp16.h>
#include <cstdint>

#define H_DIM 1024
#define S_DIM 2048
#define B_DIM 32
#define M_TILE 128
#define N_PASS 256
#define KC 64
#define NUM_G 64            // 4 passes x 16 K-chunks, one continuous pipeline

// smem layout
#define SMEM_DVEC 0
#define SMEM_VA   4096
#define SMEM_SCORE 8192
#define SMEM_STAGES 9216
#define STAGE_SZ  49152     // A fp16 16KB + B fp16 32KB
#define SMEM_B_OFF 16384
#define SMEM_TOTAL (SMEM_STAGES + 3 * STAGE_SZ)   // 156672

__device__ __align__(16) __half g_ut[(size_t)H_DIM * H_DIM];   // Ua^T fp16, 2MB
__device__ float g_dvec[B_DIM * H_DIM];

__device__ __forceinline__ uint32_t smem_u32(const void* p) {
    uint32_t a;
    asm("{ .reg .u64 t; cvta.to.shared.u64 t, %1; cvt.u32.u64 %0, t; }" : "=r"(a) : "l"(p));
    return a;
}
__device__ __forceinline__ void cp16(uint32_t s, const void* g) {
    asm volatile("cp.async.cg.shared.global [%0], [%1], 16;" :: "r"(s), "l"(g));
}
#define CP_COMMIT() asm volatile("cp.async.commit_group;" ::: "memory")
#define CP_WAIT1()  asm volatile("cp.async.wait_group 1;" ::: "memory")
#define STS128(a, r0, r1, r2, r3) \
    asm volatile("st.shared.v4.b32 [%0], {%1,%2,%3,%4};" \
                 :: "r"(a), "r"(r0), "r"(r1), "r"(r2), "r"(r3))

__device__ __forceinline__ void ldm4(uint32_t& r0, uint32_t& r1, uint32_t& r2, uint32_t& r3,
                                     uint32_t a) {
    asm volatile("ldmatrix.sync.aligned.m8n8.x4.shared.b16 {%0,%1,%2,%3}, [%4];"
                 : "=r"(r0), "=r"(r1), "=r"(r2), "=r"(r3) : "r"(a));
}
__device__ __forceinline__ void mma16816(float* c, const uint32_t* a, uint32_t b0, uint32_t b1) {
    asm volatile("mma.sync.aligned.m16n8k16.row.col.f32.f16.f16.f32 "
                 "{%0,%1,%2,%3}, {%4,%5,%6,%7}, {%8,%9}, {%0,%1,%2,%3};"
                 : "+f"(c[0]), "+f"(c[1]), "+f"(c[2]), "+f"(c[3])
                 : "r"(a[0]), "r"(a[1]), "r"(a[2]), "r"(a[3]), "r"(b0), "r"(b1));
}

// FMA/ALU-only tanh (no MUFU): exp2 range reduction + deg-5 poly + Newton rcp. abs err ~3e-5.
__device__ __forceinline__ float fast_tanh(float x) {
    x = fminf(9.0f, fmaxf(-9.0f, x));
    const float C = 2.885390082f;
    float zm = fmaf(x, C, 12582912.0f);
    int nb = __float_as_int(zm);
    float nf = zm - 12582912.0f;
    float f = fmaf(x, C, -nf);
    float p = 1.3333558e-3f;
    p = fmaf(p, f, 9.6181291e-3f);
    p = fmaf(p, f, 5.5504109e-2f);
    p = fmaf(p, f, 2.4022651e-1f);
    p = fmaf(p, f, 6.9314718e-1f);
    p = fmaf(p, f, 1.0f);
    float E = p * __int_as_float((nb + (127 - 0x4B400000)) << 23);
    float D = E + 1.0f;
    float r = __int_as_float((int)(0x7EF127EAu - (uint32_t)__float_as_int(D)));
    r = r * fmaf(-D, r, 2.0f);
    r = r * fmaf(-D, r, 2.0f);
    r = r * fmaf(-D, r, 2.0f);
    return fmaf(-2.0f, r, 1.0f);
}

// ---------------- Ut[k][h] = Ua[h][k] as fp16 ----------------
__global__ void ut_split_kernel(const float* __restrict__ ua_w) {
    __shared__ float tile[32][33];
    int tx = threadIdx.x, ty = threadIdx.y;
    int k = blockIdx.x * 32 + tx, h0 = blockIdx.y * 32;
    #pragma unroll
    for (int i = 0; i < 32; i += 8)
        tile[ty + i][tx] = ua_w[(size_t)(h0 + ty + i) * H_DIM + k];
    __syncthreads();
    #pragma unroll
    for (int i = 0; i < 32; i += 8) {
        int kk = blockIdx.x * 32 + ty + i;
        g_ut[(size_t)kk * H_DIM + h0 + tx] = __float2half(tile[tx][ty + i]);
    }
}

// ---------------- dvec[b,k] = Wa_b[k]+Ua_b[k] + sum_h dec[b,h]*Wa[h,k] ----------------
__global__ void __launch_bounds__(256) dvec_kernel(
    const float* __restrict__ dec, const float* __restrict__ wa_w,
    const float* __restrict__ wa_b, const float* __restrict__ ua_b) {
    __shared__ float ds[H_DIM];
    int b = blockIdx.x >> 2, kc = blockIdx.x & 3, tid = threadIdx.x;
    #pragma unroll
    for (int i = 0; i < 4; ++i) ds[tid + i * 256] = dec[b * H_DIM + tid + i * 256];
    __syncthreads();
    int k = kc * 256 + tid;
    float acc = wa_b[k] + ua_b[k];
    #pragma unroll 8
    for (int h = 0; h < H_DIM; ++h) acc += ds[h] * __ldg(&wa_w[(size_t)h * H_DIM + k]);
    g_dvec[b * H_DIM + k] = acc;
}

// ---------------- fused GEMM + tanh + Va-dot -> raw scores ----------------
__global__ void __launch_bounds__(256, 1) gemm_kernel(
    const float* __restrict__ enc, const float* __restrict__ va_w,
    float* __restrict__ scores) {
    extern __shared__ __align__(128) char smem[];
    uint32_t sb = smem_u32(smem);
    int tid = threadIdx.x, lane = tid & 31, wid = tid >> 5;
    int warp_m = wid >> 2, warp_n = wid & 3;
    int m0 = blockIdx.x * M_TILE;
    int bidx = m0 >> 11;

    ((float4*)(smem + SMEM_DVEC))[tid] = ((const float4*)(g_dvec + bidx * H_DIM))[tid];
    ((float4*)(smem + SMEM_VA))[tid] = ((const float4*)va_w)[tid];
    float* s_score = (float*)(smem + SMEM_SCORE);
    if (tid < 128) s_score[tid] = 0.f;
    __syncthreads();
    const float* smd = (const float*)(smem + SMEM_DVEC);
    const float* smv = (const float*)(smem + SMEM_VA);

    // hoisted ldmatrix addressing
    int r8 = lane & 7, sel = lane >> 3;
    int selb = (sel & 1) << 3, selc = sel >> 1;
    uint32_t aOff = (uint32_t)((warp_m * 64 + selb + r8) * 128);
    uint32_t bOff = (uint32_t)((warp_n * 64 + selb + r8) * 128);
    uint32_t csw[4];
    #pragma unroll
    for (int ks = 0; ks < 4; ++ks) csw[ks] = (uint32_t)(((ks * 2 + selc) ^ r8) << 4);

    // hoisted fill addressing (row/ch per thread-slot)
    int fr[4], fswA[4];
    #pragma unroll
    for (int i = 0; i < 4; ++i) {
        int idx = tid + i * 256;
        fr[i] = idx >> 3;
        int ch = idx & 7;
        fswA[i] = fr[i] * 128 + ((ch ^ (fr[i] & 7)) << 4);
    }
    int fch[4];
    #pragma unroll
    for (int i = 0; i < 4; ++i) fch[i] = (tid + i * 256) & 7;

    int brow[8], bswf[8], bch[8];
    #pragma unroll
    for (int i = 0; i < 8; ++i) {
        int idx = tid + i * 256;
        brow[i] = idx >> 3; bch[i] = idx & 7;
        bswf[i] = SMEM_B_OFF + brow[i] * 128 + ((bch[i] ^ (brow[i] & 7)) << 4);
    }

    uint32_t stage[3];
    stage[0] = sb + SMEM_STAGES;
    stage[1] = stage[0] + STAGE_SZ;
    stage[2] = stage[1] + STAGE_SZ;

    float acc[4][8][4] = {};
    float partial[8] = {};
    float4 av[8];
    uint32_t asw[4];

    // ---- prologue: stages 0,1 (g=0,1; pass 0 so n0=0) ----
    #pragma unroll
    for (int g = 0; g < 2; ++g) {
        int k0 = g * KC;
        #pragma unroll
        for (int i = 0; i < 4; ++i) {
            asw[i] = stage[g] + fswA[i];
            const float4* s = (const float4*)(enc + (size_t)(m0 + fr[i]) * H_DIM + k0 + fch[i] * 8);
            av[2 * i] = s[0]; av[2 * i + 1] = s[1];
        }
        #pragma unroll
        for (int i = 0; i < 8; ++i)
            cp16(stage[g] + bswf[i], g_ut + (size_t)brow[i] * H_DIM + k0 + bch[i] * 8);
        CP_COMMIT();
        #pragma unroll
        for (int i = 0; i < 4; ++i) {
            __half2 h0 = __floats2half2_rn(av[2 * i].x, av[2 * i].y);
            __half2 h1 = __floats2half2_rn(av[2 * i].z, av[2 * i].w);
            __half2 h2 = __floats2half2_rn(av[2 * i + 1].x, av[2 * i + 1].y);
            __half2 h3 = __floats2half2_rn(av[2 * i + 1].z, av[2 * i + 1].w);
            STS128(asw[i], *(uint32_t*)&h0, *(uint32_t*)&h1, *(uint32_t*)&h2, *(uint32_t*)&h3);
        }
    }

    // ---- main: 64 chunks, ONE barrier per chunk, 3-stage pipeline ----
    for (int g = 0; g < NUM_G; ++g) {
        CP_WAIT1();
        __syncthreads();

        int gf = g + 2;
        bool fill = gf < NUM_G;
        if (fill) {
            int k0f = (gf & 15) * KC;
            int n0f = (gf >> 4) * N_PASS;
            uint32_t stf = stage[gf % 3];
            #pragma unroll
            for (int i = 0; i < 4; ++i) {
                asw[i] = stf + fswA[i];
                const float4* s = (const float4*)(enc + (size_t)(m0 + fr[i]) * H_DIM + k0f + fch[i] * 8);
                av[2 * i] = s[0]; av[2 * i + 1] = s[1];
            }
            #pragma unroll
            for (int i = 0; i < 8; ++i)
                cp16(stf + bswf[i], g_ut + (size_t)(n0f + brow[i]) * H_DIM + k0f + bch[i] * 8);
        }
        CP_COMMIT();

        // compute current chunk
        uint32_t sA = stage[g % 3] + aOff, sB = stage[g % 3] + SMEM_B_OFF + bOff;
        #pragma unroll
        for (int ks = 0; ks < 4; ++ks) {
            uint32_t aAdr = sA + csw[ks], bAdr = sB + csw[ks];
            uint32_t a[4][4], b[4][4];
            #pragma unroll
            for (int mf = 0; mf < 4; ++mf)
                ldm4(a[mf][0], a[mf][1], a[mf][2], a[mf][3], aAdr + mf * 2048);
            #pragma unroll
            for (int nf2 = 0; nf2 < 4; ++nf2)
                ldm4(b[nf2][0], b[nf2][1], b[nf2][2], b[nf2][3], bAdr + nf2 * 2048);
            #pragma unroll
            for (int mf = 0; mf < 4; ++mf)
                #pragma unroll
                for (int nf = 0; nf < 8; ++nf)
                    mma16816(acc[mf][nf], a[mf], b[nf >> 1][nf & 1], b[nf >> 1][(nf & 1) + 2]);
        }

        // convert + store prefetched A (LDG latency hidden behind the MMAs above)
        if (fill) {
            #pragma unroll
            for (int i = 0; i < 4; ++i) {
                __half2 h0 = __floats2half2_rn(av[2 * i].x, av[2 * i].y);
                __half2 h1 = __floats2half2_rn(av[2 * i].z, av[2 * i].w);
                __half2 h2 = __floats2half2_rn(av[2 * i + 1].x, av[2 * i + 1].y);
                __half2 h3 = __floats2half2_rn(av[2 * i + 1].z, av[2 * i + 1].w);
                STS128(asw[i], *(uint32_t*)&h0, *(uint32_t*)&h1, *(uint32_t*)&h2, *(uint32_t*)&h3);
            }
        }

        // per-pass epilogue: tanh(acc + dvec) . Va, then reset accumulators
        if ((g & 15) == 15) {
            int n0 = (g >> 4) * N_PASS;
            #pragma unroll
            for (int mf = 0; mf < 4; ++mf) {
                #pragma unroll
                for (int nf = 0; nf < 8; ++nf) {
                    int col = n0 + warp_n * 64 + nf * 8 + (lane & 3) * 2;
                    float* c = acc[mf][nf];
                    partial[mf * 2 + 0] += smv[col]     * fast_tanh(c[0] + smd[col]) +
                                           smv[col + 1] * fast_tanh(c[1] + smd[col + 1]);
                    partial[mf * 2 + 1] += smv[col]     * fast_tanh(c[2] + smd[col]) +
                                           smv[col + 1] * fast_tanh(c[3] + smd[col + 1]);
                    c[0] = c[1] = c[2] = c[3] = 0.f;
                }
            }
        }
    }

    // reduce per-thread partials -> per-row scores
    #pragma unroll
    for (int p = 0; p < 8; ++p) {
        float v = partial[p];
        v += __shfl_xor_sync(0xFFFFFFFFu, v, 1);
        v += __shfl_xor_sync(0xFFFFFFFFu, v, 2);
        if ((lane & 3) == 0) {
            int row = warp_m * 64 + (p >> 1) * 16 + (p & 1) * 8 + (lane >> 2);
            atomicAdd(&s_score[row], v);
        }
    }
    __syncthreads();
    if (tid < 128) scores[m0 + tid] = s_score[tid];
}

// ---------------- masked softmax over S, in place ----------------
__global__ void __launch_bounds__(256) softmax_kernel(
    const int* __restrict__ mask, float* __restrict__ out) {
    __shared__ float red[8];
    int b = blockIdx.x, tid = threadIdx.x, wid = tid >> 5, lid = tid & 31;
    float v[8], mx = -3.0e38f;
    #pragma unroll
    for (int i = 0; i < 8; ++i) {
        int s = tid + i * 256;
        float x = out[b * S_DIM + s];
        if (mask[b * S_DIM + s] == 0) x = -1e9f;
        v[i] = x; mx = fmaxf(mx, x);
    }
    #pragma unroll
    for (int o = 16; o > 0; o >>= 1) mx = fmaxf(mx, __shfl_xor_sync(0xFFFFFFFFu, mx, o));
    if (lid == 0) red[wid] = mx;
    __syncthreads();
    mx = red[0];
    #pragma unroll
    for (int w = 1; w < 8; ++w) mx = fmaxf(mx, red[w]);
    float sum = 0.f;
    #pragma unroll
    for (int i = 0; i < 8; ++i) { v[i] = expf(v[i] - mx); sum += v[i]; }
    #pragma unroll
    for (int o = 16; o > 0; o >>= 1) sum += __shfl_xor_sync(0xFFFFFFFFu, sum, o);
    __syncthreads();
    if (lid == 0) red[wid] = sum;
    __syncthreads();
    sum = 0.f;
    #pragma unroll
    for (int w = 0; w < 8; ++w) sum += red[w];
    float inv = 1.f / sum;
    #pragma unroll
    for (int i = 0; i < 8; ++i) out[b * S_DIM + tid + i * 256] = v[i] * inv;
}

extern "C" void kernel_launch(void* const* d_in, const int* in_sizes, int n_in,
                              void* d_out, int out_size) {
    const float* dec  = (const float*)d_in[0];
    const float* enc  = (const float*)d_in[1];
    const int*   mask = (const int*)d_in[2];
    const float* wa_w = (const float*)d_in[3];
    const float* wa_b = (const float*)d_in[4];
    const float* ua_w = (const float*)d_in[5];
    const float* ua_b = (const float*)d_in[6];
    const float* va_w = (const float*)d_in[7];
    float* out = (float*)d_out;

    cudaFuncSetAttribute(gemm_kernel, cudaFuncAttributeMaxDynamicSharedMemorySize, SMEM_TOTAL);

    ut_split_kernel<<<dim3(32, 32), dim3(32, 8)>>>(ua_w);
    dvec_kernel<<<B_DIM * 4, 256>>>(dec, wa_w, wa_b, ua_b);
    gemm_kernel<<<(B_DIM * S_DIM) / M_TILE, 256, SMEM_TOTAL>>>(enc, va_w, out);
    softmax_kernel<<<B_DIM, 256>>>(mask, out);
}